// round 5
// baseline (speedup 1.0000x reference)
#include <cuda_runtime.h>
#include <math.h>

#define Bg 128
#define Lg 128
#define NNODE 16384
#define EMBD 300
#define HD 512
#define HHD 256
#define SS 10
#define NL 7
#define OUT_GE 16777216
#define OUT_OV 16908288

// ---------------- device scratch (static: allocation APIs are forbidden) ----------------
__device__ float g_xp[2][(size_t)NNODE * 1024];          // input projections per direction
__device__ float g_h[2][2][Bg * HHD];                    // [dir][parity] LSTM hidden
__device__ float g_c[2][Bg * HHD];                       // LSTM cell
__device__ float g_node[((size_t)NNODE + 1) * HD];       // node_repres (+padding row N)
__device__ float g_hid[2][2][(size_t)NNODE * HD];        // [dir][pingpong] GraphSAGE hidden
__device__ float g_mean[2][(size_t)NNODE * HD];          // neighbor means
__device__ float g_len[2][NNODE];                        // neighbor counts
__device__ float g_WhhT[2][HHD * 1024];                  // Whh^T, unit-interleaved: [k][u*4+gate]

// ---------------- init: zero LSTM state, copy padding row ----------------
__global__ void k_init(const float* __restrict__ pad) {
    int i = blockIdx.x * 256 + threadIdx.x;
    if (i < 2 * 2 * Bg * HHD) ((float*)g_h)[i] = 0.f;
    if (i < 2 * Bg * HHD)     ((float*)g_c)[i] = 0.f;
    if (i < HD) g_node[(size_t)NNODE * HD + i] = pad[i];
}

// Whh (4HH x HH, gate-major rows i,f,g,o) -> [k][unit*4+gate]
__global__ void k_prep(const float* __restrict__ WhhF, const float* __restrict__ WhhB) {
    int i = blockIdx.x * 256 + threadIdx.x;
    if (i >= 2 * HHD * 1024) return;
    int dir = i >= HHD * 1024;
    int o = dir ? i - HHD * 1024 : i;
    int k = o >> 10, c = o & 1023, u = c >> 2, g = c & 3;
    const float* W = dir ? WhhB : WhhF;
    g_WhhT[dir][o] = W[(g * HHD + u) * HHD + k];
}

// ---------------- tiled fp32 GEMM, double-buffered smem pipeline ----------------
// C[m,n] = act( sum_k A(m,k)*Bp[n,k] + bias (+bias2) )
// A(m,k): k<ksplit -> A0[(gidx?gidx[m]:m)*lda0 + k]   (gathered rows)
//         k>=ksplit -> A1[m*lda1 + k-ksplit]          (dense rows)
__global__ void __launch_bounds__(256, 2) k_gemm(
    int M, int Nn, int K,
    const float* __restrict__ A0, int lda0, const int* __restrict__ gidx,
    const float* __restrict__ A1, int lda1, int ksplit,
    const float* __restrict__ Bp, int ldb,
    const float* __restrict__ bias, const float* __restrict__ bias2,
    float* __restrict__ C, int ldc, int dorelu)
{
    __shared__ __align__(16) float As[2][8][132];
    __shared__ __align__(16) float Bs[2][8][132];
    __shared__ int roff[128];
    const int bm = blockIdx.y * 128, bn = blockIdx.x * 128;
    const int tid = threadIdx.x;
    if (tid < 128) {
        int m = bm + tid;
        roff[tid] = (m < M) ? (gidx ? gidx[m] : m) : 0;
    }
    __syncthreads();

    const int tx = tid & 15, ty = tid >> 4;
    const int lm = tid >> 1, lk = (tid & 1) * 4;
    const size_t aRow = (size_t)roff[lm] * lda0;       // gathered A row base
    const size_t aRow1 = (size_t)(bm + lm) * lda1;     // dense A row base
    const size_t bRow = (size_t)(bn + lm) * ldb;

    // tile loader: fills av/bv registers for k-chunk starting at k0
    auto load_tile = [&](int k0, float av[4], float bv[4]) {
        const int k = k0 + lk;
        av[0] = av[1] = av[2] = av[3] = 0.f;
        bv[0] = bv[1] = bv[2] = bv[3] = 0.f;
        if (k + 3 < K) {
            float4 v;
            if (k + 3 < ksplit)      v = *(const float4*)&A0[aRow + k];
            else if (k >= ksplit)    v = *(const float4*)&A1[aRow1 + (k - ksplit)];
            else {
#pragma unroll
                for (int i = 0; i < 4; i++) {
                    int kk = k + i;
                    av[i] = (kk < ksplit) ? A0[aRow + kk] : A1[aRow1 + (kk - ksplit)];
                }
                v = make_float4(av[0], av[1], av[2], av[3]);
            }
            av[0] = v.x; av[1] = v.y; av[2] = v.z; av[3] = v.w;
            float4 w = *(const float4*)&Bp[bRow + k];
            bv[0] = w.x; bv[1] = w.y; bv[2] = w.z; bv[3] = w.w;
        } else {
#pragma unroll
            for (int i = 0; i < 4; i++) {
                int kk = k + i;
                if (kk < K) {
                    av[i] = (kk < ksplit) ? A0[aRow + kk] : A1[aRow1 + (kk - ksplit)];
                    bv[i] = Bp[bRow + kk];
                }
            }
        }
    };

    float acc[8][8];
#pragma unroll
    for (int i = 0; i < 8; i++)
#pragma unroll
        for (int j = 0; j < 8; j++) acc[i][j] = 0.f;

    // preload tile 0
    float av[4], bv[4];
    load_tile(0, av, bv);
#pragma unroll
    for (int i = 0; i < 4; i++) { As[0][lk + i][lm] = av[i]; Bs[0][lk + i][lm] = bv[i]; }
    __syncthreads();

    int cur = 0;
    for (int k0 = 0; k0 < K; k0 += 8) {
        const int k1 = k0 + 8;
        const bool more = (k1 < K);
        if (more) load_tile(k1, av, bv);   // prefetch next tile into registers
#pragma unroll
        for (int kk = 0; kk < 8; kk++) {
            float4 a0 = *(const float4*)&As[cur][kk][ty * 8];
            float4 a1 = *(const float4*)&As[cur][kk][ty * 8 + 4];
            float4 b0 = *(const float4*)&Bs[cur][kk][tx * 8];
            float4 b1 = *(const float4*)&Bs[cur][kk][tx * 8 + 4];
            float a[8] = {a0.x, a0.y, a0.z, a0.w, a1.x, a1.y, a1.z, a1.w};
            float b[8] = {b0.x, b0.y, b0.z, b0.w, b1.x, b1.y, b1.z, b1.w};
#pragma unroll
            for (int i = 0; i < 8; i++)
#pragma unroll
                for (int j = 0; j < 8; j++) acc[i][j] += a[i] * b[j];
        }
        if (more) {
            const int nxt = cur ^ 1;   // last read before previous sync -> safe to overwrite
#pragma unroll
            for (int i = 0; i < 4; i++) { As[nxt][lk + i][lm] = av[i]; Bs[nxt][lk + i][lm] = bv[i]; }
            __syncthreads();
            cur = nxt;
        }
    }

#pragma unroll
    for (int i = 0; i < 8; i++) {
        int m = bm + ty * 8 + i;
        if (m >= M) continue;
#pragma unroll
        for (int j = 0; j < 8; j++) {
            int n = bn + tx * 8 + j;
            float v = acc[i][j] + bias[n] + (bias2 ? bias2[n] : 0.f);
            if (dorelu) v = fmaxf(v, 0.f);
            C[(size_t)m * ldc + n] = v;
        }
    }
}

// ---------------- one LSTM time step, both directions (blockIdx.y = dir) ----------------
// forward dir processes l=t; backward dir processes l=127-t (lax.scan reverse semantics).
__global__ void __launch_bounds__(256) k_step(int t, float* __restrict__ out) {
    const int dir = blockIdx.y;
    const int l = dir ? (Lg - 1 - t) : t;
    const int rd = t & 1, wr = rd ^ 1;
    const int bb = (blockIdx.x >> 5) * 32;   // batch tile
    const int ub = (blockIdx.x & 31) * 8;    // unit tile
    __shared__ float hs[32][257];
    const int tid = threadIdx.x;
    for (int i = tid; i < 32 * HHD; i += 256)
        hs[i >> 8][i & 255] = g_h[dir][rd][(bb + (i >> 8)) * HHD + (i & 255)];
    __syncthreads();
    const int bl = tid >> 3, ul = tid & 7;
    const int u = ub + ul, b = bb + bl;
    float ai = 0.f, af = 0.f, ag = 0.f, ao = 0.f;
    const float4* __restrict__ W = (const float4*)&g_WhhT[dir][0];
#pragma unroll 4
    for (int k = 0; k < HHD; k++) {
        float hv = hs[bl][k];
        float4 w = W[k * 256 + u];   // = g_WhhT[dir][k*1024 + u*4 .. +3]
        ai += hv * w.x; af += hv * w.y; ag += hv * w.z; ao += hv * w.w;
    }
    const int row = b * Lg + l;
    const float* __restrict__ xp = &g_xp[dir][(size_t)row * 1024];
    float gi = ai + xp[u];
    float gf = af + xp[256 + u];
    float gg = ag + xp[512 + u];
    float go = ao + xp[768 + u];
    float si = 1.f / (1.f + expf(-gi));
    float sf = 1.f / (1.f + expf(-gf));
    float so = 1.f / (1.f + expf(-go));
    float c = g_c[dir][b * HHD + u];
    c = sf * c + si * tanhf(gg);
    float h = so * tanhf(c);
    g_c[dir][b * HHD + u] = c;
    g_h[dir][wr][b * HHD + u] = h;
    g_node[(size_t)row * HD + dir * HHD + u] = h;
    out[OUT_OV + (size_t)row * HD + dir * HHD + u] = h;
}

// ---------------- neighbor lengths from node_repres (layer 0; reused thereafter) ----------
__global__ void k_len(const int* __restrict__ nodes, const int* __restrict__ fwadj,
                      const int* __restrict__ bwadj) {
    const int m = blockIdx.x, dir = blockIdx.y;
    const int* adj = dir ? bwadj : fwadj;
    __shared__ float ssum[SS];
    const int w = threadIdx.x >> 5, lane = threadIdx.x & 31;
    if (w < SS) {
        int nb = adj[(size_t)nodes[m] * SS + w];
        const float* p = &g_node[(size_t)nb * HD];
        float s = 0.f;
        for (int c = lane; c < HD; c += 32) s += fmaxf(p[c], 0.f);
#pragma unroll
        for (int o = 16; o; o >>= 1) s += __shfl_down_sync(0xffffffffu, s, o);
        if (lane == 0) ssum[w] = s;
    }
    __syncthreads();
    if (threadIdx.x == 0) {
        float cnt = 0.f;
#pragma unroll
        for (int s = 0; s < SS; s++) cnt += (ssum[s] > 0.f) ? 1.f : 0.f;
        g_len[dir][m] = cnt;
    }
}

// ---------------- neighbor mean ----------------
__global__ void k_mean(const int* __restrict__ nodes, const int* __restrict__ fwadj,
                       const int* __restrict__ bwadj,
                       const float* __restrict__ srcF, const float* __restrict__ srcB,
                       int isL0) {
    const int m = blockIdx.x, dir = blockIdx.y;
    const int* adj = dir ? bwadj : fwadj;
    const float* src = dir ? srcB : srcF;
    __shared__ int nb[SS];
    const int tid = threadIdx.x;
    if (tid < SS) nb[tid] = adj[(size_t)nodes[m] * SS + tid];
    __syncthreads();
    const int c = tid * 4;  // 128 threads x float4 = 512 cols
    float4 acc = {0.f, 0.f, 0.f, 0.f};
#pragma unroll
    for (int s = 0; s < SS; s++) {
        int ix = nb[s];
        if (!isL0 && ix == NNODE) continue;   // zero row for layers >= 1
        float4 v = *(const float4*)&src[(size_t)ix * HD + c];
        acc.x += v.x; acc.y += v.y; acc.z += v.z; acc.w += v.w;
    }
    float inv = 1.f / g_len[dir][m];
    float4 r = {acc.x * inv, acc.y * inv, acc.z * inv, acc.w * inv};
    *(float4*)&g_mean[dir][(size_t)m * HD + c] = r;
}

// ---------------- assemble hidden (B,L,1024) and maxpool ----------------
__global__ void k_hidden(float* __restrict__ out) {
    size_t i = (size_t)blockIdx.x * 256 + threadIdx.x;   // < 16777216
    int m = (int)(i >> 10), c = (int)(i & 1023);
    int dir = c >> 9, cc = c & 511;
    out[i] = g_hid[dir][0][(size_t)m * HD + cc];         // final pingpong buffer = 0
}

__global__ void k_pool(float* __restrict__ out) {
    const int b = blockIdx.x, c = threadIdx.x;           // 1024 threads
    const int dir = c >> 9, cc = c & 511;
    const float* p = &g_hid[dir][0][(size_t)(b * Lg) * HD + cc];
    float mx = -INFINITY;
    for (int l = 0; l < Lg; l++) mx = fmaxf(mx, p[(size_t)l * HD]);
    out[OUT_GE + (size_t)(b * 2 + dir) * HD + cc] = mx;
}

// ---------------- launch ----------------
extern "C" void kernel_launch(void* const* d_in, const int* in_sizes, int n_in,
                              void* d_out, int out_size) {
    (void)in_sizes; (void)n_in; (void)out_size;
    const int*   feat   = (const int*)d_in[0];
    const int*   bnodes = (const int*)d_in[1];
    const int*   fwadj  = (const int*)d_in[2];
    const int*   bwadj  = (const int*)d_in[3];
    const float* Wemb   = (const float*)d_in[4];
    const float* WihF   = (const float*)d_in[5];
    const float* WhhF   = (const float*)d_in[6];
    const float* bihF   = (const float*)d_in[7];
    const float* bhhF   = (const float*)d_in[8];
    const float* WihB   = (const float*)d_in[9];
    const float* WhhB   = (const float*)d_in[10];
    const float* bihB   = (const float*)d_in[11];
    const float* bhhB   = (const float*)d_in[12];
    const float* pad    = (const float*)d_in[13];
    const float* fwW    = (const float*)d_in[14];
    const float* fwb    = (const float*)d_in[15];
    const float* bwW    = (const float*)d_in[16];
    const float* bwb    = (const float*)d_in[17];
    float* out = (float*)d_out;

    float *p_xp, *p_node, *p_hid, *p_mean;
    cudaGetSymbolAddress((void**)&p_xp,   g_xp);
    cudaGetSymbolAddress((void**)&p_node, g_node);
    cudaGetSymbolAddress((void**)&p_hid,  g_hid);
    cudaGetSymbolAddress((void**)&p_mean, g_mean);
    const size_t NH = (size_t)NNODE * HD;
    const size_t NX = (size_t)NNODE * 1024;

    k_init<<<512, 256>>>(pad);
    k_prep<<<2048, 256>>>(WhhF, WhhB);

    // input projections (embedding gather fused via gidx = token ids)
    dim3 gX(1024 / 128, NNODE / 128);
    k_gemm<<<gX, 256>>>(NNODE, 1024, EMBD, Wemb, EMBD, feat,
                        (const float*)0, 0, EMBD, WihF, EMBD, bihF, bhhF,
                        p_xp, 1024, 0);
    k_gemm<<<gX, 256>>>(NNODE, 1024, EMBD, Wemb, EMBD, feat,
                        (const float*)0, 0, EMBD, WihB, EMBD, bihB, bhhB,
                        p_xp + NX, 1024, 0);

    // LSTM recurrence, both directions per step
    for (int t = 0; t < Lg; t++) k_step<<<dim3(128, 2), 256>>>(t, out);

    // neighbor lengths (from node_repres)
    k_len<<<dim3(NNODE, 2), 320>>>(bnodes, fwadj, bwadj);

    // GraphSAGE layers
    for (int l = 0; l < NL; l++) {
        int isL0 = (l == 0);
        const float* srcF = isL0 ? p_node : p_hid + (0 * 2 + ((l - 1) & 1)) * NH;
        const float* srcB = isL0 ? p_node : p_hid + (1 * 2 + ((l - 1) & 1)) * NH;
        k_mean<<<dim3(NNODE, 2), 128>>>(bnodes, fwadj, bwadj, srcF, srcB, isL0);
        dim3 gA(HD / 128, NNODE / 128);
        for (int dir = 0; dir < 2; dir++) {
            const float* self = isL0 ? p_node : p_hid + (dir * 2 + ((l - 1) & 1)) * NH;
            const int* gidx = isL0 ? bnodes : (const int*)0;
            const float* W  = (dir ? bwW : fwW) + (size_t)l * HD * 1024;
            const float* bb = (dir ? bwb : fwb) + (size_t)l * HD;
            const float* mn = p_mean + dir * NH;
            float* C        = p_hid + (dir * 2 + (l & 1)) * NH;
            k_gemm<<<gA, 256>>>(NNODE, HD, 1024, self, HD, gidx,
                                mn, HD, HD, W, 1024, bb, (const float*)0,
                                C, HD, 1);
        }
    }

    // outputs: hidden, graph_embedding (output_vector already written by k_step)
    k_hidden<<<65536, 256>>>(out);
    k_pool<<<128, 1024>>>(out);
}

// round 6
// speedup vs baseline: 1.0117x; 1.0117x over previous
#include <cuda_runtime.h>
#include <math.h>

#define Bg 128
#define Lg 128
#define NNODE 16384
#define EMBD 300
#define HD 512
#define HHD 256
#define SS 10
#define NL 7
#define OUT_GE 16777216
#define OUT_OV 16908288

// ---------------- device scratch (static: allocation APIs are forbidden) ----------------
__device__ float g_xp[2][(size_t)NNODE * 1024];          // input projections per direction
__device__ float g_h[2][2][Bg * HHD];                    // [dir][parity] LSTM hidden
__device__ float g_node[((size_t)NNODE + 1) * HD];       // node_repres (+padding row N)
__device__ float g_hid[2][2][(size_t)NNODE * HD];        // [dir][pingpong] GraphSAGE hidden
__device__ float g_mean[2][(size_t)NNODE * HD];          // neighbor means
__device__ float g_len[2][NNODE];                        // neighbor counts
__device__ float g_WhhT[2][HHD * 1024];                  // Whh^T, unit-interleaved: [k][u*4+gate]
__device__ unsigned g_cnt[8];                            // barrier arrival counters
__device__ volatile unsigned g_ph[8];                    // barrier phase counters

// ---------------- init: zero LSTM state + barrier state, copy padding row ----------------
__global__ void k_init(const float* __restrict__ pad) {
    int i = blockIdx.x * 256 + threadIdx.x;
    if (i < 2 * 2 * Bg * HHD) ((float*)g_h)[i] = 0.f;
    if (i < 8) { g_cnt[i] = 0u; ((unsigned*)g_ph)[i] = 0u; }
    if (i < HD) g_node[(size_t)NNODE * HD + i] = pad[i];
}

// Whh (4HH x HH, gate-major rows i,f,g,o) -> [k][unit*4+gate]
__global__ void k_prep(const float* __restrict__ WhhF, const float* __restrict__ WhhB) {
    int i = blockIdx.x * 256 + threadIdx.x;
    if (i >= 2 * HHD * 1024) return;
    int dir = i >= HHD * 1024;
    int o = dir ? i - HHD * 1024 : i;
    int k = o >> 10, c = o & 1023, u = c >> 2, g = c & 3;
    const float* W = dir ? WhhB : WhhF;
    g_WhhT[dir][o] = W[(g * HHD + u) * HHD + k];
}

// ---------------- tiled fp32 GEMM, double-buffered smem + packed f32x2 FMA ----------------
// C[m,n] = act( sum_k A(m,k)*Bp[n,k] + bias (+bias2) )
// A(m,k): k<ksplit -> A0[(gidx?gidx[m]:m)*lda0 + k]   (gathered rows)
//         k>=ksplit -> A1[m*lda1 + k-ksplit]          (dense rows)
__global__ void __launch_bounds__(256, 2) k_gemm(
    int M, int Nn, int K,
    const float* __restrict__ A0, int lda0, const int* __restrict__ gidx,
    const float* __restrict__ A1, int lda1, int ksplit,
    const float* __restrict__ Bp, int ldb,
    const float* __restrict__ bias, const float* __restrict__ bias2,
    float* __restrict__ C, int ldc, int dorelu)
{
    __shared__ __align__(16) float As[2][8][132];
    __shared__ __align__(16) float Bs[2][8][132];
    __shared__ int roff[128];
    const int bm = blockIdx.y * 128, bn = blockIdx.x * 128;
    const int tid = threadIdx.x;
    if (tid < 128) {
        int m = bm + tid;
        roff[tid] = (m < M) ? (gidx ? gidx[m] : m) : 0;
    }
    __syncthreads();

    const int tx = tid & 15, ty = tid >> 4;
    const int lm = tid >> 1, lk = (tid & 1) * 4;
    const size_t aRow = (size_t)roff[lm] * lda0;       // gathered A row base
    const size_t aRow1 = (size_t)(bm + lm) * lda1;     // dense A row base
    const size_t bRow = (size_t)(bn + lm) * ldb;

    auto load_tile = [&](int k0, float av[4], float bv[4]) {
        const int k = k0 + lk;
        av[0] = av[1] = av[2] = av[3] = 0.f;
        bv[0] = bv[1] = bv[2] = bv[3] = 0.f;
        if (k + 3 < K) {
            float4 v;
            if (k + 3 < ksplit)      v = *(const float4*)&A0[aRow + k];
            else if (k >= ksplit)    v = *(const float4*)&A1[aRow1 + (k - ksplit)];
            else {
#pragma unroll
                for (int i = 0; i < 4; i++) {
                    int kk = k + i;
                    av[i] = (kk < ksplit) ? A0[aRow + kk] : A1[aRow1 + (kk - ksplit)];
                }
                v = make_float4(av[0], av[1], av[2], av[3]);
            }
            av[0] = v.x; av[1] = v.y; av[2] = v.z; av[3] = v.w;
            float4 w = *(const float4*)&Bp[bRow + k];
            bv[0] = w.x; bv[1] = w.y; bv[2] = w.z; bv[3] = w.w;
        } else {
#pragma unroll
            for (int i = 0; i < 4; i++) {
                int kk = k + i;
                if (kk < K) {
                    av[i] = (kk < ksplit) ? A0[aRow + kk] : A1[aRow1 + (kk - ksplit)];
                    bv[i] = Bp[bRow + kk];
                }
            }
        }
    };

    // accumulators: rows i (8), column PAIRS j (4) packed in f32x2
    unsigned long long acc2[8][4];
#pragma unroll
    for (int i = 0; i < 8; i++)
#pragma unroll
        for (int j = 0; j < 4; j++) acc2[i][j] = 0ULL;

    float av[4], bv[4];
    load_tile(0, av, bv);
#pragma unroll
    for (int i = 0; i < 4; i++) { As[0][lk + i][lm] = av[i]; Bs[0][lk + i][lm] = bv[i]; }
    __syncthreads();

    int cur = 0;
    for (int k0 = 0; k0 < K; k0 += 8) {
        const int k1 = k0 + 8;
        const bool more = (k1 < K);
        if (more) load_tile(k1, av, bv);   // prefetch next tile into registers
#pragma unroll
        for (int kk = 0; kk < 8; kk++) {
            float4 a0 = *(const float4*)&As[cur][kk][ty * 8];
            float4 a1 = *(const float4*)&As[cur][kk][ty * 8 + 4];
            const ulonglong2* bp = (const ulonglong2*)&Bs[cur][kk][tx * 8];
            ulonglong2 b01 = bp[0], b23 = bp[1];
            unsigned long long bb[4] = {b01.x, b01.y, b23.x, b23.y};
            unsigned long long aa[8];
            asm("mov.b64 %0,{%1,%1};" : "=l"(aa[0]) : "f"(a0.x));
            asm("mov.b64 %0,{%1,%1};" : "=l"(aa[1]) : "f"(a0.y));
            asm("mov.b64 %0,{%1,%1};" : "=l"(aa[2]) : "f"(a0.z));
            asm("mov.b64 %0,{%1,%1};" : "=l"(aa[3]) : "f"(a0.w));
            asm("mov.b64 %0,{%1,%1};" : "=l"(aa[4]) : "f"(a1.x));
            asm("mov.b64 %0,{%1,%1};" : "=l"(aa[5]) : "f"(a1.y));
            asm("mov.b64 %0,{%1,%1};" : "=l"(aa[6]) : "f"(a1.z));
            asm("mov.b64 %0,{%1,%1};" : "=l"(aa[7]) : "f"(a1.w));
#pragma unroll
            for (int i = 0; i < 8; i++)
#pragma unroll
                for (int j = 0; j < 4; j++)
                    asm("fma.rn.f32x2 %0,%1,%2,%0;" : "+l"(acc2[i][j]) : "l"(aa[i]), "l"(bb[j]));
        }
        if (more) {
            const int nxt = cur ^ 1;   // last read before previous sync -> safe to overwrite
#pragma unroll
            for (int i = 0; i < 4; i++) { As[nxt][lk + i][lm] = av[i]; Bs[nxt][lk + i][lm] = bv[i]; }
            __syncthreads();
            cur = nxt;
        }
    }

#pragma unroll
    for (int i = 0; i < 8; i++) {
        int m = bm + ty * 8 + i;
        if (m >= M) continue;
#pragma unroll
        for (int j = 0; j < 4; j++) {
            float lo, hi;
            asm("mov.b64 {%0,%1},%2;" : "=f"(lo), "=f"(hi) : "l"(acc2[i][j]));
            int n0 = bn + tx * 8 + 2 * j;
            float v0 = lo + bias[n0]     + (bias2 ? bias2[n0]     : 0.f);
            float v1 = hi + bias[n0 + 1] + (bias2 ? bias2[n0 + 1] : 0.f);
            if (dorelu) { v0 = fmaxf(v0, 0.f); v1 = fmaxf(v1, 0.f); }
            C[(size_t)m * ldc + n0]     = v0;
            C[(size_t)m * ldc + n0 + 1] = v1;
        }
    }
}

// ---------------- persistent BiLSTM: all 128 steps in one launch ----------------
// 256 blocks = 2 dirs x 4 batch-tiles x 32 unit-tiles; all wave-1 resident.
// Per-step sync only among the 32 blocks sharing {dir, batch-tile} (group barrier).
// forward dir processes l=t; backward dir processes l=127-t (lax.scan reverse).
__global__ void __launch_bounds__(256) k_lstm(float* __restrict__ out) {
    const int dir = blockIdx.x >> 7;
    const int bi  = blockIdx.x & 127;
    const int bb  = (bi >> 5) * 32;          // batch tile base
    const int ub  = (bi & 31) * 8;           // unit tile base
    const int grp = dir * 4 + (bi >> 5);
    const int tid = threadIdx.x;
    const int bl = tid >> 3, ul = tid & 7;
    const int u = ub + ul, b = bb + bl;
    __shared__ float hs[32][257];
    float c = 0.f;                           // cell state lives in a register
    const ulonglong2* __restrict__ W2 = (const ulonglong2*)&g_WhhT[dir][0]; // [k*256+u] = float4 (i,f,g,o)

    for (int t = 0; t < Lg; t++) {
        const int l = dir ? (Lg - 1 - t) : t;
        const int rd = t & 1, wr = rd ^ 1;
        // stage h tile [32 rows][256] from global (L2-coherent loads: peers wrote it)
        for (int i = tid; i < 2048; i += 256) {
            int r = i >> 6, c4 = (i & 63) * 4;
            float4 v = __ldcg((const float4*)&g_h[dir][rd][(bb + r) * HHD + c4]);
            hs[r][c4] = v.x; hs[r][c4 + 1] = v.y; hs[r][c4 + 2] = v.z; hs[r][c4 + 3] = v.w;
        }
        __syncthreads();
        unsigned long long s01 = 0ULL, s23 = 0ULL;   // {i,f} and {g,o} gate accumulators
#pragma unroll 4
        for (int k = 0; k < HHD; k++) {
            float hv = hs[bl][k];
            unsigned long long hh;
            asm("mov.b64 %0,{%1,%1};" : "=l"(hh) : "f"(hv));
            ulonglong2 w = W2[k * 256 + u];          // L1-resident after step 0
            asm("fma.rn.f32x2 %0,%1,%2,%0;" : "+l"(s01) : "l"(hh), "l"(w.x));
            asm("fma.rn.f32x2 %0,%1,%2,%0;" : "+l"(s23) : "l"(hh), "l"(w.y));
        }
        float ai, af, ag, ao;
        asm("mov.b64 {%0,%1},%2;" : "=f"(ai), "=f"(af) : "l"(s01));
        asm("mov.b64 {%0,%1},%2;" : "=f"(ag), "=f"(ao) : "l"(s23));
        const int row = b * Lg + l;
        const float* __restrict__ xp = &g_xp[dir][(size_t)row * 1024];
        float gi = ai + xp[u];
        float gf = af + xp[256 + u];
        float gg = ag + xp[512 + u];
        float go = ao + xp[768 + u];
        float si = 1.f / (1.f + expf(-gi));
        float sf = 1.f / (1.f + expf(-gf));
        float so = 1.f / (1.f + expf(-go));
        c = sf * c + si * tanhf(gg);
        float h = so * tanhf(c);
        g_h[dir][wr][b * HHD + u] = h;
        g_node[(size_t)row * HD + dir * HHD + u] = h;
        out[OUT_OV + (size_t)row * HD + dir * HHD + u] = h;
        if (t < Lg - 1) {
            __threadfence();                 // publish h before arrival
            __syncthreads();
            if (tid == 0) {
                unsigned old = atomicAdd(&g_cnt[grp], 1u);
                if (old == 31u) {
                    g_cnt[grp] = 0u;
                    __threadfence();
                    atomicAdd((unsigned*)&g_ph[grp], 1u);
                } else {
                    while (g_ph[grp] < (unsigned)(t + 1)) __nanosleep(64);
                }
            }
            __syncthreads();
        }
    }
}

// ---------------- neighbor lengths from node_repres (layer 0; reused thereafter) ----------
__global__ void k_len(const int* __restrict__ nodes, const int* __restrict__ fwadj,
                      const int* __restrict__ bwadj) {
    const int m = blockIdx.x, dir = blockIdx.y;
    const int* adj = dir ? bwadj : fwadj;
    __shared__ float ssum[SS];
    const int w = threadIdx.x >> 5, lane = threadIdx.x & 31;
    if (w < SS) {
        int nb = adj[(size_t)nodes[m] * SS + w];
        const float* p = &g_node[(size_t)nb * HD];
        float s = 0.f;
        for (int c = lane; c < HD; c += 32) s += fmaxf(p[c], 0.f);
#pragma unroll
        for (int o = 16; o; o >>= 1) s += __shfl_down_sync(0xffffffffu, s, o);
        if (lane == 0) ssum[w] = s;
    }
    __syncthreads();
    if (threadIdx.x == 0) {
        float cnt = 0.f;
#pragma unroll
        for (int s = 0; s < SS; s++) cnt += (ssum[s] > 0.f) ? 1.f : 0.f;
        g_len[dir][m] = cnt;
    }
}

// ---------------- neighbor mean ----------------
__global__ void k_mean(const int* __restrict__ nodes, const int* __restrict__ fwadj,
                       const int* __restrict__ bwadj,
                       const float* __restrict__ srcF, const float* __restrict__ srcB,
                       int isL0) {
    const int m = blockIdx.x, dir = blockIdx.y;
    const int* adj = dir ? bwadj : fwadj;
    const float* src = dir ? srcB : srcF;
    __shared__ int nb[SS];
    const int tid = threadIdx.x;
    if (tid < SS) nb[tid] = adj[(size_t)nodes[m] * SS + tid];
    __syncthreads();
    const int c = tid * 4;  // 128 threads x float4 = 512 cols
    float4 acc = {0.f, 0.f, 0.f, 0.f};
#pragma unroll
    for (int s = 0; s < SS; s++) {
        int ix = nb[s];
        if (!isL0 && ix == NNODE) continue;   // zero row for layers >= 1
        float4 v = *(const float4*)&src[(size_t)ix * HD + c];
        acc.x += v.x; acc.y += v.y; acc.z += v.z; acc.w += v.w;
    }
    float inv = 1.f / g_len[dir][m];
    float4 r = {acc.x * inv, acc.y * inv, acc.z * inv, acc.w * inv};
    *(float4*)&g_mean[dir][(size_t)m * HD + c] = r;
}

// ---------------- assemble hidden (B,L,1024) and maxpool ----------------
__global__ void k_hidden(float* __restrict__ out) {
    size_t i = (size_t)blockIdx.x * 256 + threadIdx.x;   // < 16777216
    int m = (int)(i >> 10), c = (int)(i & 1023);
    int dir = c >> 9, cc = c & 511;
    out[i] = g_hid[dir][0][(size_t)m * HD + cc];         // final pingpong buffer = 0
}

__global__ void k_pool(float* __restrict__ out) {
    const int b = blockIdx.x, c = threadIdx.x;           // 1024 threads
    const int dir = c >> 9, cc = c & 511;
    const float* p = &g_hid[dir][0][(size_t)(b * Lg) * HD + cc];
    float mx = -INFINITY;
    for (int l = 0; l < Lg; l++) mx = fmaxf(mx, p[(size_t)l * HD]);
    out[OUT_GE + (size_t)(b * 2 + dir) * HD + cc] = mx;
}

// ---------------- launch ----------------
extern "C" void kernel_launch(void* const* d_in, const int* in_sizes, int n_in,
                              void* d_out, int out_size) {
    (void)in_sizes; (void)n_in; (void)out_size;
    const int*   feat   = (const int*)d_in[0];
    const int*   bnodes = (const int*)d_in[1];
    const int*   fwadj  = (const int*)d_in[2];
    const int*   bwadj  = (const int*)d_in[3];
    const float* Wemb   = (const float*)d_in[4];
    const float* WihF   = (const float*)d_in[5];
    const float* WhhF   = (const float*)d_in[6];
    const float* bihF   = (const float*)d_in[7];
    const float* bhhF   = (const float*)d_in[8];
    const float* WihB   = (const float*)d_in[9];
    const float* WhhB   = (const float*)d_in[10];
    const float* bihB   = (const float*)d_in[11];
    const float* bhhB   = (const float*)d_in[12];
    const float* pad    = (const float*)d_in[13];
    const float* fwW    = (const float*)d_in[14];
    const float* fwb    = (const float*)d_in[15];
    const float* bwW    = (const float*)d_in[16];
    const float* bwb    = (const float*)d_in[17];
    float* out = (float*)d_out;

    float *p_xp, *p_node, *p_hid, *p_mean;
    cudaGetSymbolAddress((void**)&p_xp,   g_xp);
    cudaGetSymbolAddress((void**)&p_node, g_node);
    cudaGetSymbolAddress((void**)&p_hid,  g_hid);
    cudaGetSymbolAddress((void**)&p_mean, g_mean);
    const size_t NH = (size_t)NNODE * HD;
    const size_t NX = (size_t)NNODE * 1024;

    k_init<<<512, 256>>>(pad);
    k_prep<<<2048, 256>>>(WhhF, WhhB);

    // input projections (embedding gather fused via gidx = token ids)
    dim3 gX(1024 / 128, NNODE / 128);
    k_gemm<<<gX, 256>>>(NNODE, 1024, EMBD, Wemb, EMBD, feat,
                        (const float*)0, 0, EMBD, WihF, EMBD, bihF, bhhF,
                        p_xp, 1024, 0);
    k_gemm<<<gX, 256>>>(NNODE, 1024, EMBD, Wemb, EMBD, feat,
                        (const float*)0, 0, EMBD, WihB, EMBD, bihB, bhhB,
                        p_xp + NX, 1024, 0);

    // BiLSTM: single persistent kernel, all 128 steps
    k_lstm<<<256, 256>>>(out);

    // neighbor lengths (from node_repres)
    k_len<<<dim3(NNODE, 2), 320>>>(bnodes, fwadj, bwadj);

    // GraphSAGE layers
    for (int l = 0; l < NL; l++) {
        int isL0 = (l == 0);
        const float* srcF = isL0 ? p_node : p_hid + (0 * 2 + ((l - 1) & 1)) * NH;
        const float* srcB = isL0 ? p_node : p_hid + (1 * 2 + ((l - 1) & 1)) * NH;
        k_mean<<<dim3(NNODE, 2), 128>>>(bnodes, fwadj, bwadj, srcF, srcB, isL0);
        dim3 gA(HD / 128, NNODE / 128);
        for (int dir = 0; dir < 2; dir++) {
            const float* self = isL0 ? p_node : p_hid + (dir * 2 + ((l - 1) & 1)) * NH;
            const int* gidx = isL0 ? bnodes : (const int*)0;
            const float* W  = (dir ? bwW : fwW) + (size_t)l * HD * 1024;
            const float* bb = (dir ? bwb : fwb) + (size_t)l * HD;
            const float* mn = p_mean + dir * NH;
            float* C        = p_hid + (dir * 2 + (l & 1)) * NH;
            k_gemm<<<gA, 256>>>(NNODE, HD, 1024, self, HD, gidx,
                                mn, HD, HD, W, 1024, bb, (const float*)0,
                                C, HD, 1);
        }
    }

    // outputs: hidden, graph_embedding (output_vector already written by k_lstm)
    k_hidden<<<65536, 256>>>(out);
    k_pool<<<128, 1024>>>(out);
}

// round 16
// speedup vs baseline: 1.3349x; 1.3195x over previous
#include <cuda_runtime.h>
#include <cuda_bf16.h>
#include <math.h>

#define Bg 128
#define Lg 128
#define NNODE 16384
#define EMBD 300
#define HD 512
#define HHD 256
#define SS 10
#define NL 7
#define OUT_GE 16777216
#define OUT_OV 16908288

// ---------------- device scratch (static: allocation APIs are forbidden) ----------------
__device__ float g_xp[2][(size_t)NNODE * 1024];          // input projections per direction
__device__ float g_h[2][2][Bg * HHD];                    // [dir][parity] LSTM hidden
__device__ float g_node[((size_t)NNODE + 1) * HD];       // node_repres (+padding row N)
__device__ float g_hid[2][2][(size_t)NNODE * HD];        // [dir][pingpong] GraphSAGE hidden
__device__ float g_len[2][NNODE];                        // neighbor counts
__device__ float g_WhhT[2][HHD * 1024];                  // Whh^T, unit-interleaved
__device__ unsigned g_cnt[8];
__device__ volatile unsigned g_ph[8];
// bf16 (as ushort) operand buffers for tensor-core GEMM
__device__ unsigned short g_Ah[2][2][(size_t)NNODE * 1024];  // [dir][parity] A hi
__device__ unsigned short g_Al[2][2][(size_t)NNODE * 1024];  // [dir][parity] A lo
__device__ unsigned short g_Wh[2][(size_t)NL * HD * 1024];   // weights hi
__device__ unsigned short g_Wl[2][(size_t)NL * HD * 1024];   // weights lo

// ---------------- helpers ----------------
__device__ __forceinline__ unsigned smem_u32(const void* p) {
    unsigned a;
    asm("{ .reg .u64 t; cvta.to.shared.u64 t, %1; cvt.u32.u64 %0, t; }" : "=r"(a) : "l"(p));
    return a;
}
__device__ __forceinline__ void f2bf(float x, unsigned short& hi, unsigned short& lo) {
    __nv_bfloat16 h = __float2bfloat16(x);
    hi = __bfloat16_as_ushort(h);
    lo = __bfloat16_as_ushort(__float2bfloat16(x - __bfloat162float(h)));
}
#define LDSM4(R, ADDR) \
    asm volatile("ldmatrix.sync.aligned.m8n8.x4.shared.b16 {%0,%1,%2,%3},[%4];" \
        : "=r"((R)[0]), "=r"((R)[1]), "=r"((R)[2]), "=r"((R)[3]) : "r"(ADDR))
#define MMA16816(D, A, B0, B1) \
    asm volatile("mma.sync.aligned.m16n8k16.row.col.f32.bf16.bf16.f32 " \
        "{%0,%1,%2,%3},{%4,%5,%6,%7},{%8,%9},{%0,%1,%2,%3};" \
        : "+f"((D)[0]), "+f"((D)[1]), "+f"((D)[2]), "+f"((D)[3]) \
        : "r"((A)[0]), "r"((A)[1]), "r"((A)[2]), "r"((A)[3]), "r"(B0), "r"(B1))

// ---------------- init ----------------
__global__ void k_init(const float* __restrict__ pad) {
    int i = blockIdx.x * 256 + threadIdx.x;
    if (i < 2 * 2 * Bg * HHD) ((float*)g_h)[i] = 0.f;
    if (i < 8) { g_cnt[i] = 0u; ((unsigned*)g_ph)[i] = 0u; }
    if (i < HD) g_node[(size_t)NNODE * HD + i] = pad[i];
}

__global__ void k_prep(const float* __restrict__ WhhF, const float* __restrict__ WhhB) {
    int i = blockIdx.x * 256 + threadIdx.x;
    if (i >= 2 * HHD * 1024) return;
    int dir = i >= HHD * 1024;
    int o = dir ? i - HHD * 1024 : i;
    int k = o >> 10, c = o & 1023, u = c >> 2, g = c & 3;
    const float* W = dir ? WhhB : WhhF;
    g_WhhT[dir][o] = W[(g * HHD + u) * HHD + k];
}

// weights fp32 -> bf16 hi/lo
__global__ void k_cvtW(const float* __restrict__ fwW, const float* __restrict__ bwW) {
    size_t i = (size_t)blockIdx.x * 256 + threadIdx.x;
    const size_t NW = (size_t)NL * HD * 1024;
    if (i >= 2 * NW / 4) return;
    int dir = i >= NW / 4;
    size_t j = (dir ? i - NW / 4 : i) * 4;
    const float4 v = *(const float4*)&(dir ? bwW : fwW)[j];
    unsigned short h0, l0, h1, l1, h2, l2, h3, l3;
    f2bf(v.x, h0, l0); f2bf(v.y, h1, l1); f2bf(v.z, h2, l2); f2bf(v.w, h3, l3);
    uint2 ph = make_uint2((unsigned)h0 | ((unsigned)h1 << 16), (unsigned)h2 | ((unsigned)h3 << 16));
    uint2 pl = make_uint2((unsigned)l0 | ((unsigned)l1 << 16), (unsigned)l2 | ((unsigned)l3 << 16));
    *(uint2*)&g_Wh[dir][j] = ph;
    *(uint2*)&g_Wl[dir][j] = pl;
}

// layer-0 self operand: node_repres gathered by bnodes -> A[dir][0] cols 0..511 (both dirs)
__global__ void k_cvtN(const int* __restrict__ bnodes) {
    size_t i = (size_t)blockIdx.x * 256 + threadIdx.x;
    if (i >= (size_t)NNODE * 128) return;
    int m = (int)(i >> 7), c = (int)(i & 127) * 4;
    const float4 v = *(const float4*)&g_node[(size_t)bnodes[m] * HD + c];
    unsigned short h0, l0, h1, l1, h2, l2, h3, l3;
    f2bf(v.x, h0, l0); f2bf(v.y, h1, l1); f2bf(v.z, h2, l2); f2bf(v.w, h3, l3);
    uint2 ph = make_uint2((unsigned)h0 | ((unsigned)h1 << 16), (unsigned)h2 | ((unsigned)h3 << 16));
    uint2 pl = make_uint2((unsigned)l0 | ((unsigned)l1 << 16), (unsigned)l2 | ((unsigned)l3 << 16));
    size_t o = (size_t)m * 1024 + c;
    *(uint2*)&g_Ah[0][0][o] = ph;  *(uint2*)&g_Al[0][0][o] = pl;
    *(uint2*)&g_Ah[1][0][o] = ph;  *(uint2*)&g_Al[1][0][o] = pl;
}

// ---------------- fp32 GEMM (input projections only), double-buffered + f32x2 ----------------
__global__ void __launch_bounds__(256, 2) k_gemm(
    int M, int Nn, int K,
    const float* __restrict__ A0, int lda0, const int* __restrict__ gidx,
    const float* __restrict__ Bp, int ldb,
    const float* __restrict__ bias, const float* __restrict__ bias2,
    float* __restrict__ C, int ldc)
{
    __shared__ __align__(16) float As[2][8][132];
    __shared__ __align__(16) float Bs[2][8][132];
    __shared__ int roff[128];
    const int bm = blockIdx.y * 128, bn = blockIdx.x * 128;
    const int tid = threadIdx.x;
    if (tid < 128) {
        int m = bm + tid;
        roff[tid] = (m < M) ? (gidx ? gidx[m] : m) : 0;
    }
    __syncthreads();
    const int tx = tid & 15, ty = tid >> 4;
    const int lm = tid >> 1, lk = (tid & 1) * 4;
    const size_t aRow = (size_t)roff[lm] * lda0;
    const size_t bRow = (size_t)(bn + lm) * ldb;

    auto load_tile = [&](int k0, float av[4], float bv[4]) {
        const int k = k0 + lk;
        av[0] = av[1] = av[2] = av[3] = 0.f;
        bv[0] = bv[1] = bv[2] = bv[3] = 0.f;
        if (k + 3 < K) {
            float4 v = *(const float4*)&A0[aRow + k];
            av[0] = v.x; av[1] = v.y; av[2] = v.z; av[3] = v.w;
            float4 w = *(const float4*)&Bp[bRow + k];
            bv[0] = w.x; bv[1] = w.y; bv[2] = w.z; bv[3] = w.w;
        } else {
#pragma unroll
            for (int i = 0; i < 4; i++) {
                int kk = k + i;
                if (kk < K) { av[i] = A0[aRow + kk]; bv[i] = Bp[bRow + kk]; }
            }
        }
    };

    unsigned long long acc2[8][4];
#pragma unroll
    for (int i = 0; i < 8; i++)
#pragma unroll
        for (int j = 0; j < 4; j++) acc2[i][j] = 0ULL;

    float av[4], bv[4];
    load_tile(0, av, bv);
#pragma unroll
    for (int i = 0; i < 4; i++) { As[0][lk + i][lm] = av[i]; Bs[0][lk + i][lm] = bv[i]; }
    __syncthreads();

    int cur = 0;
    for (int k0 = 0; k0 < K; k0 += 8) {
        const bool more = (k0 + 8 < K);
        if (more) load_tile(k0 + 8, av, bv);
#pragma unroll
        for (int kk = 0; kk < 8; kk++) {
            float4 a0 = *(const float4*)&As[cur][kk][ty * 8];
            float4 a1 = *(const float4*)&As[cur][kk][ty * 8 + 4];
            const ulonglong2* bp = (const ulonglong2*)&Bs[cur][kk][tx * 8];
            ulonglong2 b01 = bp[0], b23 = bp[1];
            unsigned long long bb[4] = {b01.x, b01.y, b23.x, b23.y};
            unsigned long long aa[8];
            asm("mov.b64 %0,{%1,%1};" : "=l"(aa[0]) : "f"(a0.x));
            asm("mov.b64 %0,{%1,%1};" : "=l"(aa[1]) : "f"(a0.y));
            asm("mov.b64 %0,{%1,%1};" : "=l"(aa[2]) : "f"(a0.z));
            asm("mov.b64 %0,{%1,%1};" : "=l"(aa[3]) : "f"(a0.w));
            asm("mov.b64 %0,{%1,%1};" : "=l"(aa[4]) : "f"(a1.x));
            asm("mov.b64 %0,{%1,%1};" : "=l"(aa[5]) : "f"(a1.y));
            asm("mov.b64 %0,{%1,%1};" : "=l"(aa[6]) : "f"(a1.z));
            asm("mov.b64 %0,{%1,%1};" : "=l"(aa[7]) : "f"(a1.w));
#pragma unroll
            for (int i = 0; i < 8; i++)
#pragma unroll
                for (int j = 0; j < 4; j++)
                    asm("fma.rn.f32x2 %0,%1,%2,%0;" : "+l"(acc2[i][j]) : "l"(aa[i]), "l"(bb[j]));
        }
        if (more) {
            const int nxt = cur ^ 1;
#pragma unroll
            for (int i = 0; i < 4; i++) { As[nxt][lk + i][lm] = av[i]; Bs[nxt][lk + i][lm] = bv[i]; }
            __syncthreads();
            cur = nxt;
        }
    }
#pragma unroll
    for (int i = 0; i < 8; i++) {
        int m = bm + ty * 8 + i;
        if (m >= M) continue;
#pragma unroll
        for (int j = 0; j < 4; j++) {
            float lo, hi;
            asm("mov.b64 {%0,%1},%2;" : "=f"(lo), "=f"(hi) : "l"(acc2[i][j]));
            int n0 = bn + tx * 8 + 2 * j;
            C[(size_t)m * ldc + n0]     = lo + bias[n0]     + bias2[n0];
            C[(size_t)m * ldc + n0 + 1] = hi + bias[n0 + 1] + bias2[n0 + 1];
        }
    }
}

// ---------------- HMMA bf16-split GEMM: C[128x128 tile] = relu(A(16384x1024) W^T + b) ----
// mma.sync m16n8k16 bf16, fp32 accum. A = Ah+Al hi/lo split; C = Ah*Bh + Ah*Bl + Al*Bh.
// 8 warps: 4 (m) x 2 (n); warp tile 32x64. K-chunks of 32 bf16 staged in padded smem.
// Epilogue writes fp32 C and next layer's bf16 hi/lo self operand.
__global__ void __launch_bounds__(256) k_sage(
    const unsigned short* __restrict__ Ah_, const unsigned short* __restrict__ Al_,
    const unsigned short* __restrict__ Wh_, const unsigned short* __restrict__ Wl_,
    const float* __restrict__ bias, float* __restrict__ C,
    unsigned short* __restrict__ Aoh, unsigned short* __restrict__ Aol)
{
    __shared__ __align__(16) unsigned short sAh[128 * 40];  // 40-elem row stride: conflict-free LDSM
    __shared__ __align__(16) unsigned short sAl[128 * 40];
    __shared__ __align__(16) unsigned short sBh[128 * 40];
    __shared__ __align__(16) unsigned short sBl[128 * 40];
    const int tid = threadIdx.x, lane = tid & 31, wid = tid >> 5;
    const int bm = blockIdx.y * 128, n0 = blockIdx.x * 128;
    const int mw = wid & 3, nw = wid >> 2;     // warp tile origin: (mw*32, nw*64)
    const int g = lane >> 2, t = lane & 3;
    const int q = lane >> 3, p = lane & 7;

    float acc[2][8][4];
#pragma unroll
    for (int a = 0; a < 2; a++)
#pragma unroll
        for (int b = 0; b < 8; b++)
#pragma unroll
            for (int d = 0; d < 4; d++) acc[a][b][d] = 0.f;

    // ldmatrix per-lane base addresses (bytes)
    const unsigned aoff = (((mw * 32 + ((q & 1) << 3) + p) * 40 + ((q >> 1) << 3)) << 1);
    const unsigned boff = (((nw * 64 + ((q >> 1) << 3) + p) * 40 + ((q & 1) << 3)) << 1);
    const unsigned aBH = smem_u32(sAh) + aoff;
    const unsigned aBL = smem_u32(sAl) + aoff;
    const unsigned bBH = smem_u32(sBh) + boff;
    const unsigned bBL = smem_u32(sBl) + boff;

    const int s0 = tid * 2;
    for (int c = 0; c < 32; c++) {
#pragma unroll
        for (int e = 0; e < 2; e++) {
            int s = s0 + e, r = s >> 2, sc = (s & 3) << 3;
            size_t ga = (size_t)(bm + r) * 1024 + c * 32 + sc;
            size_t gb = (size_t)(n0 + r) * 1024 + c * 32 + sc;
            int d = r * 40 + sc;
            *(uint4*)&sAh[d] = *(const uint4*)&Ah_[ga];
            *(uint4*)&sAl[d] = *(const uint4*)&Al_[ga];
            *(uint4*)&sBh[d] = *(const uint4*)&Wh_[gb];
            *(uint4*)&sBl[d] = *(const uint4*)&Wl_[gb];
        }
        __syncthreads();
#pragma unroll
        for (int kk = 0; kk < 2; kk++) {
            const unsigned ko = kk * 32;   // 16 bf16 = 32 bytes
            unsigned ah[2][4], al[2][4];
            LDSM4(ah[0], aBH + ko);            // m-tile 0 (rows +0)
            LDSM4(ah[1], aBH + 1280 + ko);     // m-tile 1 (rows +16 = 16*40*2 bytes)
            LDSM4(al[0], aBL + ko);
            LDSM4(al[1], aBL + 1280 + ko);
#pragma unroll
            for (int jp = 0; jp < 4; jp++) {   // n-tile pairs (2 x n8 each)
                unsigned bh[4], bl[4];
                LDSM4(bh, bBH + jp * 1280 + ko);
                LDSM4(bl, bBL + jp * 1280 + ko);
#pragma unroll
                for (int mt = 0; mt < 2; mt++) {
                    MMA16816(acc[mt][2 * jp],     ah[mt], bh[0], bh[1]);
                    MMA16816(acc[mt][2 * jp + 1], ah[mt], bh[2], bh[3]);
                    MMA16816(acc[mt][2 * jp],     al[mt], bh[0], bh[1]);
                    MMA16816(acc[mt][2 * jp + 1], al[mt], bh[2], bh[3]);
                    MMA16816(acc[mt][2 * jp],     ah[mt], bl[0], bl[1]);
                    MMA16816(acc[mt][2 * jp + 1], ah[mt], bl[2], bl[3]);
                }
            }
        }
        __syncthreads();
    }

    // epilogue: bias + relu -> fp32 C ; bf16 hi/lo -> next layer's A operand
#pragma unroll
    for (int mt = 0; mt < 2; mt++) {
#pragma unroll
        for (int nt = 0; nt < 8; nt++) {
            const int m = bm + mw * 32 + mt * 16 + g;
            const int n = n0 + nw * 64 + nt * 8 + t * 2;
            const float b0 = bias[n], b1 = bias[n + 1];
            float v0 = fmaxf(acc[mt][nt][0] + b0, 0.f);
            float v1 = fmaxf(acc[mt][nt][1] + b1, 0.f);
            float v2 = fmaxf(acc[mt][nt][2] + b0, 0.f);
            float v3 = fmaxf(acc[mt][nt][3] + b1, 0.f);
            C[(size_t)m * HD + n] = v0;
            C[(size_t)m * HD + n + 1] = v1;
            C[(size_t)(m + 8) * HD + n] = v2;
            C[(size_t)(m + 8) * HD + n + 1] = v3;
            unsigned short h0, l0, h1, l1;
            f2bf(v0, h0, l0); f2bf(v1, h1, l1);
            size_t o = (size_t)m * 1024 + n;
            *(unsigned*)&Aoh[o] = (unsigned)h0 | ((unsigned)h1 << 16);
            *(unsigned*)&Aol[o] = (unsigned)l0 | ((unsigned)l1 << 16);
            f2bf(v2, h0, l0); f2bf(v3, h1, l1);
            o = (size_t)(m + 8) * 1024 + n;
            *(unsigned*)&Aoh[o] = (unsigned)h0 | ((unsigned)h1 << 16);
            *(unsigned*)&Aol[o] = (unsigned)l0 | ((unsigned)l1 << 16);
        }
    }
}

// ---------------- persistent BiLSTM ----------------
__global__ void __launch_bounds__(256) k_lstm(float* __restrict__ out) {
    const int dir = blockIdx.x >> 7;
    const int bi  = blockIdx.x & 127;
    const int bb  = (bi >> 5) * 32;
    const int ub  = (bi & 31) * 8;
    const int grp = dir * 4 + (bi >> 5);
    const int tid = threadIdx.x;
    const int bl = tid >> 3, ul = tid & 7;
    const int u = ub + ul, b = bb + bl;
    __shared__ float hs[32][257];
    float c = 0.f;
    const ulonglong2* __restrict__ W2 = (const ulonglong2*)&g_WhhT[dir][0];

    for (int t = 0; t < Lg; t++) {
        const int l = dir ? (Lg - 1 - t) : t;
        const int rd = t & 1, wr = rd ^ 1;
        for (int i = tid; i < 2048; i += 256) {
            int r = i >> 6, c4 = (i & 63) * 4;
            float4 v = __ldcg((const float4*)&g_h[dir][rd][(bb + r) * HHD + c4]);
            hs[r][c4] = v.x; hs[r][c4 + 1] = v.y; hs[r][c4 + 2] = v.z; hs[r][c4 + 3] = v.w;
        }
        __syncthreads();
        unsigned long long s01 = 0ULL, s23 = 0ULL;
#pragma unroll 4
        for (int k = 0; k < HHD; k++) {
            float hv = hs[bl][k];
            unsigned long long hh;
            asm("mov.b64 %0,{%1,%1};" : "=l"(hh) : "f"(hv));
            ulonglong2 w = W2[k * 256 + u];
            asm("fma.rn.f32x2 %0,%1,%2,%0;" : "+l"(s01) : "l"(hh), "l"(w.x));
            asm("fma.rn.f32x2 %0,%1,%2,%0;" : "+l"(s23) : "l"(hh), "l"(w.y));
        }
        float ai, af, ag, ao;
        asm("mov.b64 {%0,%1},%2;" : "=f"(ai), "=f"(af) : "l"(s01));
        asm("mov.b64 {%0,%1},%2;" : "=f"(ag), "=f"(ao) : "l"(s23));
        const int row = b * Lg + l;
        const float* __restrict__ xp = &g_xp[dir][(size_t)row * 1024];
        float gi = ai + xp[u];
        float gf = af + xp[256 + u];
        float gg = ag + xp[512 + u];
        float go = ao + xp[768 + u];
        float si = 1.f / (1.f + expf(-gi));
        float sf = 1.f / (1.f + expf(-gf));
        float so = 1.f / (1.f + expf(-go));
        c = sf * c + si * tanhf(gg);
        float h = so * tanhf(c);
        g_h[dir][wr][b * HHD + u] = h;
        g_node[(size_t)row * HD + dir * HHD + u] = h;
        out[OUT_OV + (size_t)row * HD + dir * HHD + u] = h;
        if (t < Lg - 1) {
            __threadfence();
            __syncthreads();
            if (tid == 0) {
                unsigned old = atomicAdd(&g_cnt[grp], 1u);
                if (old == 31u) {
                    g_cnt[grp] = 0u;
                    __threadfence();
                    atomicAdd((unsigned*)&g_ph[grp], 1u);
                } else {
                    while (g_ph[grp] < (unsigned)(t + 1)) __nanosleep(64);
                }
            }
            __syncthreads();
        }
    }
}

// ---------------- neighbor lengths ----------------
__global__ void k_len(const int* __restrict__ nodes, const int* __restrict__ fwadj,
                      const int* __restrict__ bwadj) {
    const int m = blockIdx.x, dir = blockIdx.y;
    const int* adj = dir ? bwadj : fwadj;
    __shared__ float ssum[SS];
    const int w = threadIdx.x >> 5, lane = threadIdx.x & 31;
    if (w < SS) {
        int nb = adj[(size_t)nodes[m] * SS + w];
        const float* p = &g_node[(size_t)nb * HD];
        float s = 0.f;
        for (int c = lane; c < HD; c += 32) s += fmaxf(p[c], 0.f);
#pragma unroll
        for (int o = 16; o; o >>= 1) s += __shfl_down_sync(0xffffffffu, s, o);
        if (lane == 0) ssum[w] = s;
    }
    __syncthreads();
    if (threadIdx.x == 0) {
        float cnt = 0.f;
#pragma unroll
        for (int s = 0; s < SS; s++) cnt += (ssum[s] > 0.f) ? 1.f : 0.f;
        g_len[dir][m] = cnt;
    }
}

// ---------------- neighbor mean -> bf16 hi/lo into A buffer cols [512..1024) -------------
__global__ void k_mean(const int* __restrict__ nodes, const int* __restrict__ fwadj,
                       const int* __restrict__ bwadj,
                       const float* __restrict__ srcF, const float* __restrict__ srcB,
                       int isL0,
                       unsigned short* __restrict__ AhF, unsigned short* __restrict__ AlF,
                       unsigned short* __restrict__ AhB, unsigned short* __restrict__ AlB) {
    const int m = blockIdx.x, dir = blockIdx.y;
    const int* adj = dir ? bwadj : fwadj;
    const float* src = dir ? srcB : srcF;
    __shared__ int nb[SS];
    const int tid = threadIdx.x;
    if (tid < SS) nb[tid] = adj[(size_t)nodes[m] * SS + tid];
    __syncthreads();
    const int c = tid * 4;
    float4 acc = {0.f, 0.f, 0.f, 0.f};
#pragma unroll
    for (int s = 0; s < SS; s++) {
        int ix = nb[s];
        if (!isL0 && ix == NNODE) continue;
        float4 v = *(const float4*)&src[(size_t)ix * HD + c];
        acc.x += v.x; acc.y += v.y; acc.z += v.z; acc.w += v.w;
    }
    float inv = 1.f / g_len[dir][m];
    float r0 = acc.x * inv, r1 = acc.y * inv, r2 = acc.z * inv, r3 = acc.w * inv;
    unsigned short h0, l0, h1, l1, h2, l2, h3, l3;
    f2bf(r0, h0, l0); f2bf(r1, h1, l1); f2bf(r2, h2, l2); f2bf(r3, h3, l3);
    uint2 ph = make_uint2((unsigned)h0 | ((unsigned)h1 << 16), (unsigned)h2 | ((unsigned)h3 << 16));
    uint2 pl = make_uint2((unsigned)l0 | ((unsigned)l1 << 16), (unsigned)l2 | ((unsigned)l3 << 16));
    size_t o = (size_t)m * 1024 + 512 + c;
    if (dir) { *(uint2*)&AhB[o] = ph; *(uint2*)&AlB[o] = pl; }
    else     { *(uint2*)&AhF[o] = ph; *(uint2*)&AlF[o] = pl; }
}

// ---------------- outputs ----------------
__global__ void k_hidden(float* __restrict__ out) {
    size_t i = (size_t)blockIdx.x * 256 + threadIdx.x;
    int m = (int)(i >> 10), c = (int)(i & 1023);
    int dir = c >> 9, cc = c & 511;
    out[i] = g_hid[dir][0][(size_t)m * HD + cc];
}

__global__ void k_pool(float* __restrict__ out) {
    const int b = blockIdx.x, c = threadIdx.x;
    const int dir = c >> 9, cc = c & 511;
    const float* p = &g_hid[dir][0][(size_t)(b * Lg) * HD + cc];
    float mx = -INFINITY;
    for (int l = 0; l < Lg; l++) mx = fmaxf(mx, p[(size_t)l * HD]);
    out[OUT_GE + (size_t)(b * 2 + dir) * HD + cc] = mx;
}

// ---------------- launch ----------------
extern "C" void kernel_launch(void* const* d_in, const int* in_sizes, int n_in,
                              void* d_out, int out_size) {
    (void)in_sizes; (void)n_in; (void)out_size;
    const int*   feat   = (const int*)d_in[0];
    const int*   bnodes = (const int*)d_in[1];
    const int*   fwadj  = (const int*)d_in[2];
    const int*   bwadj  = (const int*)d_in[3];
    const float* Wemb   = (const float*)d_in[4];
    const float* WihF   = (const float*)d_in[5];
    const float* WhhF   = (const float*)d_in[6];
    const float* bihF   = (const float*)d_in[7];
    const float* bhhF   = (const float*)d_in[8];
    const float* WihB   = (const float*)d_in[9];
    const float* WhhB   = (const float*)d_in[10];
    const float* bihB   = (const float*)d_in[11];
    const float* bhhB   = (const float*)d_in[12];
    const float* pad    = (const float*)d_in[13];
    const float* fwW    = (const float*)d_in[14];
    const float* fwb    = (const float*)d_in[15];
    const float* bwW    = (const float*)d_in[16];
    const float* bwb    = (const float*)d_in[17];
    float* out = (float*)d_out;

    float *p_xp, *p_node, *p_hid;
    unsigned short *p_Ah, *p_Al, *p_Wh, *p_Wl;
    cudaGetSymbolAddress((void**)&p_xp,   g_xp);
    cudaGetSymbolAddress((void**)&p_node, g_node);
    cudaGetSymbolAddress((void**)&p_hid,  g_hid);
    cudaGetSymbolAddress((void**)&p_Ah,   g_Ah);
    cudaGetSymbolAddress((void**)&p_Al,   g_Al);
    cudaGetSymbolAddress((void**)&p_Wh,   g_Wh);
    cudaGetSymbolAddress((void**)&p_Wl,   g_Wl);

    const size_t NH = (size_t)NNODE * HD;
    const size_t NX = (size_t)NNODE * 1024;
    const size_t NW = (size_t)NL * HD * 1024;

    k_init<<<512, 256>>>(pad);
    k_prep<<<2048, 256>>>(WhhF, WhhB);
    k_cvtW<<<(unsigned)((2 * NW / 4 + 255) / 256), 256>>>(fwW, bwW);

    // input projections (embedding gather fused via gidx = token ids)
    dim3 gX(1024 / 128, NNODE / 128);
    k_gemm<<<gX, 256>>>(NNODE, 1024, EMBD, Wemb, EMBD, feat, WihF, EMBD, bihF, bhhF, p_xp, 1024);
    k_gemm<<<gX, 256>>>(NNODE, 1024, EMBD, Wemb, EMBD, feat, WihB, EMBD, bihB, bhhB, p_xp + NX, 1024);

    // BiLSTM persistent
    k_lstm<<<256, 256>>>(out);

    k_len<<<dim3(NNODE, 2), 320>>>(bnodes, fwadj, bwadj);
    k_cvtN<<<(NNODE * 128 + 255) / 256, 256>>>(bnodes);

    // GraphSAGE layers via HMMA (mma.sync) split-bf16 GEMM
    dim3 gS(HD / 128, NNODE / 128);
    for (int l = 0; l < NL; l++) {
        int isL0 = (l == 0);
        int pa = l & 1, pn = pa ^ 1;
        const float* srcF = isL0 ? p_node : p_hid + (0 * 2 + ((l - 1) & 1)) * NH;
        const float* srcB = isL0 ? p_node : p_hid + (1 * 2 + ((l - 1) & 1)) * NH;
        k_mean<<<dim3(NNODE, 2), 128>>>(bnodes, fwadj, bwadj, srcF, srcB, isL0,
                                        p_Ah + (0 * 2 + pa) * NX, p_Al + (0 * 2 + pa) * NX,
                                        p_Ah + (1 * 2 + pa) * NX, p_Al + (1 * 2 + pa) * NX);
        for (int dir = 0; dir < 2; dir++) {
            k_sage<<<gS, 256>>>(
                p_Ah + (dir * 2 + pa) * NX, p_Al + (dir * 2 + pa) * NX,
                p_Wh + dir * NW + (size_t)l * HD * 1024,
                p_Wl + dir * NW + (size_t)l * HD * 1024,
                (dir ? bwb : fwb) + (size_t)l * HD,
                p_hid + (dir * 2 + (l & 1)) * NH,
                p_Ah + (dir * 2 + pn) * NX, p_Al + (dir * 2 + pn) * NX);
        }
    }

    k_hidden<<<65536, 256>>>(out);
    k_pool<<<128, 1024>>>(out);
}